// round 3
// baseline (speedup 1.0000x reference)
#include <cuda_runtime.h>

// Dilation1D: out[r] = max_{j=0..10} x[r-5+j] + h[j],  h[j] = -(j-5)^2/(4*scale)
// Symmetric-tap form: out[r] = max(x[r], max_{d=1..5} max(x[r-d],x[r+d]) + h_d)
// VEC=16 per thread: 8 aligned float4 loads (32 floats) -> 16 outputs,
// halving the L1 load amplification vs VEC=8 (2.0x vs 3.0x).

#define VEC   16
#define BLOCK 256

__global__ __launch_bounds__(BLOCK) void dilate1d_kernel(
    const float* __restrict__ x,
    const float* __restrict__ scale_p,
    float* __restrict__ out,
    int n)
{
    int i = (blockIdx.x * BLOCK + threadIdx.x) * VEC;
    if (i >= n) return;

    const float s = *scale_p;
    const float c = -0.25f / s;
    const float h1 =  1.0f * c;
    const float h2 =  4.0f * c;
    const float h3 =  9.0f * c;
    const float h4 = 16.0f * c;
    const float h5 = 25.0f * c;

    const float NEG_INF = __int_as_float(0xff800000);

    // Window w[k] = x[i - 8 + k], k = 0..31.
    // Outputs v=0..15 need x[i+v-5 .. i+v+5] = w[v+3 .. v+13]; max idx 28 < 32.
    float w[32];

    if (i >= 8 && i + 24 <= n) {
        // Fast path: 8 aligned float4 loads (i multiple of 16 -> 64B aligned base).
        const float4* p = reinterpret_cast<const float4*>(x + i - 8);
        #pragma unroll
        for (int q = 0; q < 8; q++) {
            float4 v = p[q];
            w[q * 4 + 0] = v.x;
            w[q * 4 + 1] = v.y;
            w[q * 4 + 2] = v.z;
            w[q * 4 + 3] = v.w;
        }
    } else {
        // Boundary path: scalar loads with -inf padding (matches reference).
        #pragma unroll
        for (int k = 0; k < 32; k++) {
            int idx = i - 8 + k;
            w[k] = (idx >= 0 && idx < n) ? x[idx] : NEG_INF;
        }
    }

    float o[VEC];
    #pragma unroll
    for (int v = 0; v < VEC; v++) {
        float r = w[v + 8];                              // center tap, h=0
        r = fmaxf(r, fmaxf(w[v + 7], w[v + 9])  + h1);
        r = fmaxf(r, fmaxf(w[v + 6], w[v + 10]) + h2);
        r = fmaxf(r, fmaxf(w[v + 5], w[v + 11]) + h3);
        r = fmaxf(r, fmaxf(w[v + 4], w[v + 12]) + h4);
        r = fmaxf(r, fmaxf(w[v + 3], w[v + 13]) + h5);
        o[v] = r;
    }

    if (i + VEC <= n) {
        float4* po = reinterpret_cast<float4*>(out + i);
        #pragma unroll
        for (int q = 0; q < 4; q++)
            po[q] = make_float4(o[q*4+0], o[q*4+1], o[q*4+2], o[q*4+3]);
    } else {
        #pragma unroll
        for (int v = 0; v < VEC; v++) {
            if (i + v < n) out[i + v] = o[v];
        }
    }
}

extern "C" void kernel_launch(void* const* d_in, const int* in_sizes, int n_in,
                              void* d_out, int out_size)
{
    const float* x       = (const float*)d_in[0];
    const float* scale_p = (const float*)d_in[1];
    float*       out     = (float*)d_out;
    int n = in_sizes[0];

    int threads = (n + VEC - 1) / VEC;
    int blocks  = (threads + BLOCK - 1) / BLOCK;
    dilate1d_kernel<<<blocks, BLOCK>>>(x, scale_p, out, n);
}

// round 6
// speedup vs baseline: 1.1405x; 1.1405x over previous
#include <cuda_runtime.h>

// Dilation1D: out[r] = max_{j=0..10} x[r-5+j] + h[j],  h[j] = -(j-5)^2/(4*scale)
// Symmetric-tap form: out[r] = max(x[r], max_{d=1..5} max(x[r-d],x[r+d]) + h_d)
//
// VEC=4: lane stride = 16B = float4, so every LDG.128/STG.128 is perfectly
// coalesced (4 wavefronts each, the structural L1tex minimum). Halo re-reads
// between neighboring threads hit L1/L2 (verified R1: DRAM traffic == compulsory).

#define VEC   4
#define BLOCK 256

__global__ __launch_bounds__(BLOCK) void dilate1d_kernel(
    const float* __restrict__ x,
    const float* __restrict__ scale_p,
    float* __restrict__ out,
    int n)
{
    int i = (blockIdx.x * BLOCK + threadIdx.x) * VEC;
    if (i >= n) return;

    const float s = *scale_p;
    const float c = -0.25f / s;
    const float h1 =  1.0f * c;
    const float h2 =  4.0f * c;
    const float h3 =  9.0f * c;
    const float h4 = 16.0f * c;
    const float h5 = 25.0f * c;

    const float NEG_INF = __int_as_float(0xff800000);

    // Window w[k] = x[i - 8 + k], k = 0..19.
    // Output v (0..3) needs x[i+v-5 .. i+v+5] = w[v+3 .. v+13]; max idx 16 < 20.
    float w[20];

    if (i >= 8 && i + 12 <= n) {
        // Fast path: 5 perfectly-coalesced float4 loads.
        const float4* p = reinterpret_cast<const float4*>(x + i - 8);
        #pragma unroll
        for (int q = 0; q < 5; q++) {
            float4 v = p[q];
            w[q * 4 + 0] = v.x;
            w[q * 4 + 1] = v.y;
            w[q * 4 + 2] = v.z;
            w[q * 4 + 3] = v.w;
        }
    } else {
        // Boundary path: scalar guarded loads with -inf padding (matches reference).
        #pragma unroll
        for (int k = 0; k < 20; k++) {
            int idx = i - 8 + k;
            w[k] = (idx >= 0 && idx < n) ? x[idx] : NEG_INF;
        }
    }

    float o[VEC];
    #pragma unroll
    for (int v = 0; v < VEC; v++) {
        float r = w[v + 8];                              // center tap, h=0
        r = fmaxf(r, fmaxf(w[v + 7], w[v + 9])  + h1);
        r = fmaxf(r, fmaxf(w[v + 6], w[v + 10]) + h2);
        r = fmaxf(r, fmaxf(w[v + 5], w[v + 11]) + h3);
        r = fmaxf(r, fmaxf(w[v + 4], w[v + 12]) + h4);
        r = fmaxf(r, fmaxf(w[v + 3], w[v + 13]) + h5);
        o[v] = r;
    }

    if (i + VEC <= n) {
        // Streaming store: output is never re-read; keep it out of L2's way.
        float4 ov = make_float4(o[0], o[1], o[2], o[3]);
        __stcs(reinterpret_cast<float4*>(out + i), ov);
    } else {
        #pragma unroll
        for (int v = 0; v < VEC; v++) {
            if (i + v < n) out[i + v] = o[v];
        }
    }
}

extern "C" void kernel_launch(void* const* d_in, const int* in_sizes, int n_in,
                              void* d_out, int out_size)
{
    const float* x       = (const float*)d_in[0];
    const float* scale_p = (const float*)d_in[1];
    float*       out     = (float*)d_out;
    int n = in_sizes[0];

    int threads = (n + VEC - 1) / VEC;
    int blocks  = (threads + BLOCK - 1) / BLOCK;
    dilate1d_kernel<<<blocks, BLOCK>>>(x, scale_p, out, n);
}